// round 12
// baseline (speedup 1.0000x reference)
#include <cuda_runtime.h>
#include <cstdint>

// TPT-SVF IIR — two-phase exact-boundary scan.
// R12 (= R11 + compile fix): K2 single resident wave: 2048 blocks x 64 thr
// (2 warps = 2 batch halves of one 64-sample chunk), intra-warp double-buffered
// tiles. K1: GROUP=128 for 2x parallelism of the latency-bound state walk.
// Fix: tail cp.async.wait_group uses literal immediates (asm "n" needs ICE).

#define NSAMP   131072
#define BATCH   64
#define GROUP   128
#define WARM    96
#define K1TILE  32
#define K1TILES ((GROUP + WARM) / K1TILE)    // 7
#define NGROUPS (NSAMP / GROUP)              // 1024
#define C2      64
#define NCH2    (NSAMP / C2)                 // 2048

__device__ float2 g_states[NCH2 * BATCH];    // 1MB scratch (exact chunk-start states)

__device__ __forceinline__ uint32_t smem_u32(const void* p) {
    return (uint32_t)__cvta_generic_to_shared(p);
}

// ---- coefficient folding ----
struct Coef {
    float a00, a01, a10, a11, b0, b1;
    float q00, q01, q10, q11;                          // A^4
    float ab0, ab1, a2b0, a2b1, a3b0, a3b1;
    float e0, e1, ex, ea0, ea1, ea20, ea21, ea30, ea31;
    float eb, eab, ea2b;
};

__device__ __forceinline__ Coef fold(const float* gp, const float* twoRp,
                                     const float* mixp) {
    Coef k;
    const float g    = *gp;
    const float twoR = *twoRp;
    const float m0 = mixp[0], m1 = mixp[1], m2 = mixp[2];

    const float T   = 1.0f / (1.0f + g * (g + twoR));
    const float h00 = T,      h01 = -g * T;
    const float h10 = g * T,  h11 = (twoR * g + 1.0f) * T;
    const float gb0 = g * T,  gb1 = g * g * T;

    k.a00 = 2.0f * h00 - 1.0f; k.a01 = 2.0f * h01;
    k.a10 = 2.0f * h10;        k.a11 = 2.0f * h11 - 1.0f;
    k.b0  = 2.0f * gb0;        k.b1  = 2.0f * gb1;

    const float c0 = twoR * (m0 - m2);
    const float c1 = m1 - m2;
    const float cx = m2;
    k.e0 = c0 * h00 + c1 * h10;
    k.e1 = c0 * h01 + c1 * h11;
    k.ex = c0 * gb0 + c1 * gb1 + cx;

    k.ea0  = k.e0 * k.a00 + k.e1 * k.a10;     k.ea1  = k.e0 * k.a01 + k.e1 * k.a11;
    k.ea20 = k.ea0 * k.a00 + k.ea1 * k.a10;   k.ea21 = k.ea0 * k.a01 + k.ea1 * k.a11;
    k.ea30 = k.ea20 * k.a00 + k.ea21 * k.a10; k.ea31 = k.ea20 * k.a01 + k.ea21 * k.a11;

    k.eb   = k.e0 * k.b0 + k.e1 * k.b1;
    k.eab  = k.ea0 * k.b0 + k.ea1 * k.b1;
    k.ea2b = k.ea20 * k.b0 + k.ea21 * k.b1;

    k.ab0  = k.a00 * k.b0 + k.a01 * k.b1;     k.ab1  = k.a10 * k.b0 + k.a11 * k.b1;
    k.a2b0 = k.a00 * k.ab0 + k.a01 * k.ab1;   k.a2b1 = k.a10 * k.ab0 + k.a11 * k.ab1;
    k.a3b0 = k.a00 * k.a2b0 + k.a01 * k.a2b1; k.a3b1 = k.a10 * k.a2b0 + k.a11 * k.a2b1;

    const float p00 = k.a00 * k.a00 + k.a01 * k.a10, p01 = k.a00 * k.a01 + k.a01 * k.a11;
    const float p10 = k.a10 * k.a00 + k.a11 * k.a10, p11 = k.a10 * k.a01 + k.a11 * k.a11;
    k.q00 = p00 * p00 + p01 * p10; k.q01 = p00 * p01 + p01 * p11;
    k.q10 = p10 * p00 + p11 * p10; k.q11 = p10 * p01 + p11 * p11;
    return k;
}

// =================== K1: boundary-state walk ===================
__global__ __launch_bounds__(32, 16) void svf_states_kernel(
    const float* __restrict__ audio,
    const float* __restrict__ gp,
    const float* __restrict__ twoRp,
    const float* __restrict__ mixp)
{
    __shared__ float4 sm[3][32 * 8];          // 3 x 4KB

    const int lane  = threadIdx.x;
    const int group = blockIdx.x >> 1;
    const int rbase = (blockIdx.x & 1) * 32;
    const int base  = group * GROUP - WARM;

    const Coef K = fold(gp, twoRp, mixp);

    const uint32_t smemBase = smem_u32(&sm[0][0]);
    const uint32_t compBase = smemBase + ((uint32_t)lane << 7)
                            + (((uint32_t)lane & 7u) << 4);
    const uint32_t r0   = (uint32_t)(lane >> 3);
    const uint32_t cc   = (uint32_t)(lane & 7);
    const uint32_t stgA = smemBase + (r0 << 7) + ((cc ^ r0) << 4);
    const uint32_t stgB = stgA ^ 64u;
    const float* gsrc0 = audio + (size_t)(rbase + (int)r0) * NSAMP + 4 * (int)cc + base;

    auto stage = [&](int t, uint32_t bufOff) {
        if (base + t * K1TILE >= 0) {
            const float* src = gsrc0 + t * K1TILE;
            #pragma unroll
            for (int kk = 0; kk < 8; ++kk) {
                const uint32_t d = ((kk & 1) ? stgB : stgA) + bufOff + (uint32_t)(kk * 512);
                asm volatile("cp.async.cg.shared.global [%0], [%1], 16;\n"
                             :: "r"(d), "l"(src + (size_t)(4 * kk) * NSAMP));
            }
        }
        asm volatile("cp.async.commit_group;\n");
    };

    float s0 = 0.0f, s1 = 0.0f;

    auto walk_tile = [&](uint32_t bufOff, bool active) {
        if (active) {
            const uint32_t cb = compBase + bufOff;
            #pragma unroll
            for (int c = 0; c < 8; ++c) {
                float4 x;
                asm volatile("ld.shared.v4.f32 {%0,%1,%2,%3}, [%4];"
                             : "=f"(x.x), "=f"(x.y), "=f"(x.z), "=f"(x.w)
                             : "r"(cb ^ (uint32_t)(c << 4)));
                const float n0 = fmaf(K.q00, s0, fmaf(K.q01, s1,
                                 fmaf(K.a3b0, x.x, fmaf(K.a2b0, x.y,
                                 fmaf(K.ab0, x.z, K.b0 * x.w)))));
                const float n1 = fmaf(K.q10, s0, fmaf(K.q11, s1,
                                 fmaf(K.a3b1, x.x, fmaf(K.a2b1, x.y,
                                 fmaf(K.ab1, x.z, K.b1 * x.w)))));
                s0 = n0; s1 = n1;
            }
        }
    };

    stage(0, 0);
    stage(1, 4096);
    stage(2, 8192);

    const int cbase = group * (GROUP / C2);        // first 64-chunk index of group

    #pragma unroll
    for (int t = 0; t < K1TILES; ++t) {
        const uint32_t bufOff = (uint32_t)(t % 3) * 4096u;
        // states at 64-sample chunk starts: tiles 3 and 5 (t-3 even)
        if (t >= 3 && ((t - 3) & 1) == 0)
            g_states[(size_t)(cbase + ((t - 3) >> 1)) * BATCH + rbase + lane] =
                make_float2(s0, s1);
        if (t + 3 < K1TILES) {
            asm volatile("cp.async.wait_group 2;\n" ::: "memory");
            __syncwarp();
            walk_tile(bufOff, base + t * K1TILE >= 0);
            stage(t + 3, bufOff);
        } else {
            // tail: remaining in-flight groups after tile t = K1TILES-1-t (literal)
            if (t == K1TILES - 3)
                asm volatile("cp.async.wait_group 2;\n" ::: "memory");
            else if (t == K1TILES - 2)
                asm volatile("cp.async.wait_group 1;\n" ::: "memory");
            else
                asm volatile("cp.async.wait_group 0;\n" ::: "memory");
            __syncwarp();
            walk_tile(bufOff, base + t * K1TILE >= 0);
        }
    }
}

// =================== K2: per-chunk outputs, no warm-up ===================
// block = 64 thr (2 warps = 2 batch halves of the same 64-sample chunk);
// each warp double-buffers its two 32-sample tiles.
__global__ __launch_bounds__(64, 14) void svf_out_kernel(
    const float* __restrict__ audio,
    const float* __restrict__ gp,
    const float* __restrict__ twoRp,
    const float* __restrict__ mixp,
    float* __restrict__ out)
{
    __shared__ float4 sm[2][2][32 * 8];        // [warp][buf] 4KB each = 16KB

    const int tid   = threadIdx.x;
    const int lane  = tid & 31;
    const int w     = tid >> 5;
    const int chunk = blockIdx.x;
    const int rbase = w * 32;
    const int pos0  = chunk * C2;

    const uint32_t smemBase = smem_u32(&sm[w][0][0]);
    const uint32_t r0   = (uint32_t)(lane >> 3);
    const uint32_t cc   = (uint32_t)(lane & 7);
    const uint32_t stgA = smemBase + (r0 << 7) + ((cc ^ r0) << 4);
    const uint32_t stgB = stgA ^ 64u;
    const float* gsrc0 = audio + (size_t)(rbase + (int)r0) * NSAMP + 4 * (int)cc + pos0;
    float*       gdst0 = out   + (size_t)(rbase + (int)r0) * NSAMP + 4 * (int)cc + pos0;

    // kick both tile loads immediately; fold constants while they fly
    #pragma unroll
    for (int t = 0; t < 2; ++t) {
        #pragma unroll
        for (int kk = 0; kk < 8; ++kk) {
            const uint32_t d = ((kk & 1) ? stgB : stgA)
                             + (uint32_t)(t * 4096) + (uint32_t)(kk * 512);
            asm volatile("cp.async.cg.shared.global [%0], [%1], 16;\n"
                         :: "r"(d), "l"(gsrc0 + t * K1TILE + (size_t)(4 * kk) * NSAMP));
        }
        asm volatile("cp.async.commit_group;\n");
    }

    const float2 st = g_states[(size_t)chunk * BATCH + rbase + lane];
    float s0 = st.x, s1 = st.y;

    const Coef K = fold(gp, twoRp, mixp);

    const uint32_t compBase = smemBase + ((uint32_t)lane << 7)
                            + (((uint32_t)lane & 7u) << 4);

    #pragma unroll
    for (int t = 0; t < 2; ++t) {
        if (t == 0) asm volatile("cp.async.wait_group 1;\n" ::: "memory");
        else        asm volatile("cp.async.wait_group 0;\n" ::: "memory");
        __syncwarp();

        const uint32_t cb = compBase + (uint32_t)(t * 4096);
        #pragma unroll
        for (int c = 0; c < 8; ++c) {
            const uint32_t a = cb ^ (uint32_t)(c << 4);
            float4 x;
            asm volatile("ld.shared.v4.f32 {%0,%1,%2,%3}, [%4];"
                         : "=f"(x.x), "=f"(x.y), "=f"(x.z), "=f"(x.w)
                         : "r"(a));
            float4 o;
            o.x = fmaf(K.e0, s0, fmaf(K.e1, s1, K.ex * x.x));
            o.y = fmaf(K.ea0, s0, fmaf(K.ea1, s1,
                  fmaf(K.eb, x.x, K.ex * x.y)));
            o.z = fmaf(K.ea20, s0, fmaf(K.ea21, s1,
                  fmaf(K.eab, x.x, fmaf(K.eb, x.y, K.ex * x.z))));
            o.w = fmaf(K.ea30, s0, fmaf(K.ea31, s1,
                  fmaf(K.ea2b, x.x, fmaf(K.eab, x.y, fmaf(K.eb, x.z, K.ex * x.w)))));
            const float n0 = fmaf(K.q00, s0, fmaf(K.q01, s1,
                             fmaf(K.a3b0, x.x, fmaf(K.a2b0, x.y,
                             fmaf(K.ab0, x.z, K.b0 * x.w)))));
            const float n1 = fmaf(K.q10, s0, fmaf(K.q11, s1,
                             fmaf(K.a3b1, x.x, fmaf(K.a2b1, x.y,
                             fmaf(K.ab1, x.z, K.b1 * x.w)))));
            s0 = n0; s1 = n1;
            asm volatile("st.shared.v4.f32 [%0], {%1,%2,%3,%4};"
                         :: "r"(a), "f"(o.x), "f"(o.y), "f"(o.z), "f"(o.w));
        }
        __syncwarp();

        float* dst = gdst0 + t * K1TILE;
        #pragma unroll
        for (int kk = 0; kk < 8; ++kk) {
            const uint32_t sa = ((kk & 1) ? stgB : stgA)
                              + (uint32_t)(t * 4096) + (uint32_t)(kk * 512);
            float4 v;
            asm volatile("ld.shared.v4.f32 {%0,%1,%2,%3}, [%4];"
                         : "=f"(v.x), "=f"(v.y), "=f"(v.z), "=f"(v.w)
                         : "r"(sa));
            *(float4*)(dst + (size_t)(4 * kk) * NSAMP) = v;
        }
    }
}

extern "C" void kernel_launch(void* const* d_in, const int* in_sizes, int n_in,
                              void* d_out, int out_size) {
    const float* audio = (const float*)d_in[0];
    const float* g     = (const float*)d_in[1];
    const float* twoR  = (const float*)d_in[2];
    const float* mix   = (const float*)d_in[3];
    float* outp        = (float*)d_out;

    static bool carveout_set = false;
    if (!carveout_set) {
        cudaFuncSetAttribute(svf_states_kernel, cudaFuncAttributePreferredSharedMemoryCarveout,
                             cudaSharedmemCarveoutMaxShared);
        cudaFuncSetAttribute(svf_out_kernel, cudaFuncAttributePreferredSharedMemoryCarveout,
                             cudaSharedmemCarveoutMaxShared);
        carveout_set = true;
    }

    svf_states_kernel<<<NGROUPS * 2, 32>>>(audio, g, twoR, mix);
    svf_out_kernel<<<NCH2, 64>>>(audio, g, twoR, mix, outp);
}